// round 2
// baseline (speedup 1.0000x reference)
#include <cuda_runtime.h>
#include <cuda_bf16.h>

// DeformableConvLayer: B=4, H=W=256, C=64, K=3x3, UNITS=1.
// One warp processes 8 consecutive pixels of one row.
//  - kernel weights: loaded once per warp into registers (float2/lane/tap)
//  - base-tap mask values: 3x10 register tile per warp, distributed via shuffle
//  - per pixel: lanes 0..8 compute the 9 deformable tap coords (exact reference
//    semantics: joint padded-index-grid zeroing, mask compare at padded coords,
//    offset gated by mask diff, floor+clip, padded-input sample)
//  - gathers: 9 x warp-coalesced float2 (256B) loads + FMA
//  - butterfly reduce leaves sum on all lanes -> lane p keeps pixel p,
//    one coalesced 8-lane store per warp.

namespace {

constexpr int Hc = 256;
constexpr int Wc = 256;
constexpr int Cc = 64;
constexpr int PPW = 8;                         // pixels per warp
constexpr int WARPS = 8;
constexpr int THREADS = WARPS * 32;            // 256
constexpr int PIX_TOTAL = 4 * Hc * Wc;         // 262144
constexpr int PIX_PER_BLOCK = WARPS * PPW;     // 64
constexpr int BLOCKS = PIX_TOTAL / PIX_PER_BLOCK;  // 4096

__global__ __launch_bounds__(THREADS)
void dcn_warp8(const float* __restrict__ input,    // [4,256,256,64]
               const float* __restrict__ mask,     // [256,256]
               const float* __restrict__ offset,   // [pix,18]
               const float* __restrict__ kern,     // [9,64]
               const float* __restrict__ bias,
               float* __restrict__ out)            // [pix]
{
    const unsigned FULL = 0xffffffffu;
    const int lane = threadIdx.x & 31;
    const int warp = threadIdx.x >> 5;

    const int pixBase = blockIdx.x * PIX_PER_BLOCK + warp * PPW;
    const int b  = pixBase >> 16;
    const int h  = (pixBase >> 8) & 255;
    const int w0 = pixBase & 255;              // row-aligned: w0..w0+7 same row

    // ---- weights once per warp: tap k, channels {2*lane, 2*lane+1} ----
    float2 wk[9];
#pragma unroll
    for (int k = 0; k < 9; k++)
        wk[k] = *reinterpret_cast<const float2*>(kern + k * Cc + 2 * lane);
    const float biasV = __ldg(bias);

    // ---- base-mask register tile: rows h-2..h (3), cols w0-2..w0+7 (10) ----
    // p_mask(tap ky,kx; pixel p) = mask[yb-1, xb-1] iff yb,xb in [1,255], else 0,
    // where yb=h+ky-1, xb=(w0+p)+kx-1.  row=yb-1=(h-2)+ky, col=xb-1=(w0-2)+(p+kx).
    float mval = 0.0f;
    {
        const int r = lane / 10;
        const int c = lane - r * 10;
        const int row = h - 2 + r;
        const int col = w0 - 2 + c;
        if (lane < 30 && row >= 0 && row <= 254 && col >= 0 && col <= 254)
            mval = mask[row * Wc + col];
    }

    const float* inp = input + (size_t)b * (Hc * Wc * Cc) + 2 * lane;

    float myres = 0.0f;

    for (int p = 0; p < PPW; p++) {
        const int pix = pixBase + p;
        const int w   = w0 + p;

        // offsets: 18 contiguous floats on lanes 0..17, fan out by shuffle
        float offv = 0.0f;
        if (lane < 18) offv = offset[(size_t)pix * 18 + lane];
        const float y_off = __shfl_sync(FULL, offv, (2 * lane) & 31);
        const float x_off = __shfl_sync(FULL, offv, (2 * lane + 1) & 31);

        // tap coordinates (meaningful on lanes 0..8)
        const int kk = (lane < 9) ? lane : 0;
        const int ky = kk / 3;
        const int kx = kk - ky * 3;
        const int yb = h + ky - 1;
        const int xb = w + kx - 1;
        const bool inb = (yb >= 0) & (yb < Hc) & (xb >= 0) & (xb < Wc);
        const int yi = inb ? yb : 0;
        const int xi = inb ? xb : 0;

        // base mask value from the register tile
        const float p_mask = __shfl_sync(FULL, mval, ky * 10 + p + kx);

        // mask at offset point (padded coords, floor + clip to [0,257])
        int yo = (int)floorf((float)yi + y_off);
        int xo = (int)floorf((float)xi + x_off);
        yo = min(max(yo, 0), Hc + 1);
        xo = min(max(xo, 0), Wc + 1);
        float p_mask_off = 0.0f;
        if (lane < 9 && yo >= 1 && yo <= Hc && xo >= 1 && xo <= Wc)
            p_mask_off = mask[(yo - 1) * Wc + (xo - 1)];

        const float diff = (p_mask != p_mask_off) ? 1.0f : 0.0f;

        const float yf = fminf(fmaxf((float)yi + y_off * diff, 0.0f), 255.0f);
        const float xf = fminf(fmaxf((float)xi + x_off * diff, 0.0f), 255.0f);
        const int y0 = (int)floorf(yf);
        const int x0 = (int)floorf(xf);

        // sample padded input: zero when y0==0 || x0==0, else input[y0-1, x0-1]
        int packed = -1;
        if (y0 >= 1 && x0 >= 1)
            packed = ((y0 - 1) << 8) | (x0 - 1);

        // coalesced gathers + FMA
        float acc = 0.0f;
#pragma unroll
        for (int k = 0; k < 9; k++) {
            const int pk = __shfl_sync(FULL, packed, k);
            if (pk >= 0) {
                const float2 v = *reinterpret_cast<const float2*>(inp + pk * Cc);
                acc = fmaf(v.x, wk[k].x, acc);
                acc = fmaf(v.y, wk[k].y, acc);
            }
        }

        // butterfly reduce: every lane ends with the full sum
#pragma unroll
        for (int s = 16; s; s >>= 1)
            acc += __shfl_xor_sync(FULL, acc, s);

        if (lane == p) myres = acc + biasV;
    }

    // one coalesced store per warp
    if (lane < PPW)
        out[pixBase + lane] = myres;
}

} // namespace

extern "C" void kernel_launch(void* const* d_in, const int* in_sizes, int n_in,
                              void* d_out, int out_size)
{
    const float* input  = (const float*)d_in[0];
    const float* mask   = (const float*)d_in[1];
    const float* offset = (const float*)d_in[2];
    const float* kern   = (const float*)d_in[3];
    const float* bias   = (const float*)d_in[4];
    float* out = (float*)d_out;

    dcn_warp8<<<BLOCKS, THREADS>>>(input, mask, offset, kern, bias, out);
}